// round 6
// baseline (speedup 1.0000x reference)
#include <cuda_runtime.h>
#include <cuda_bf16.h>

// Problem constants
#define BB 64      // batch
#define NN 512     // tokens
#define EE 512     // embed dim
#define DD 1024    // 2E
#define TT 64      // decode steps
#define NB 128     // persistent grid
#define NT 256     // persistent block

// ---------------- device scratch ----------------
__device__ float g_enc[(size_t)BB * EE * NN];   // [b][e][n]  64 MB, L2-resident
__device__ float g_dec_t[DD * BB];              // decoder input, TRANSPOSED [k][b]
__device__ float g_gpart[4][3][EE][BB];         // gate partials [kq][gate][e][b]
__device__ float g_hx_t[EE * BB];               // hx transposed [e(=k')][b]
__device__ float g_qpart[4][BB][EE];            // q partials [ks][b][e]
__device__ float g_scores[BB * NN];
__device__ unsigned g_bar_cnt;                  // grid barrier state (self-cleaning)
__device__ volatile unsigned g_bar_epoch;

// ---------------- packed fp32x2 helpers (sm_103a FFMA2) ----------------
__device__ __forceinline__ unsigned long long pack2(float x, float y) {
    unsigned long long r;
    asm("mov.b64 %0, {%1,%2};" : "=l"(r) : "f"(x), "f"(y));
    return r;
}
__device__ __forceinline__ void unpack2(unsigned long long v, float& x, float& y) {
    asm("mov.b64 {%0,%1}, %2;" : "=f"(x), "=f"(y) : "l"(v));
}
__device__ __forceinline__ void ffma2(unsigned long long& d, unsigned long long a, unsigned long long b) {
    asm("fma.rn.f32x2 %0, %1, %2, %0;" : "+l"(d) : "l"(a), "l"(b));
}
__device__ __forceinline__ float ex2a(float x) {
    float r; asm("ex2.approx.f32 %0, %1;" : "=f"(r) : "f"(x)); return r;
}
__device__ __forceinline__ float rcpa(float x) {
    float r; asm("rcp.approx.f32 %0, %1;" : "=f"(r) : "f"(x)); return r;
}
__device__ __forceinline__ float ldcg(const float* p) {
    float r; asm volatile("ld.global.cg.f32 %0, [%1];" : "=f"(r) : "l"(p)); return r;
}
__device__ __forceinline__ float4 ldcg4(const float* p) {
    float4 v;
    asm volatile("ld.global.cg.v4.f32 {%0,%1,%2,%3}, [%4];"
                 : "=f"(v.x), "=f"(v.y), "=f"(v.z), "=f"(v.w) : "l"(p));
    return v;
}

#define C2L 2.885390081777926f   // 2*log2(e)

// ---------------- grid-wide barrier (all NB blocks co-resident) ----------------
__device__ __forceinline__ void grid_barrier() {
    __syncthreads();
    if (threadIdx.x == 0) {
        __threadfence();
        const unsigned e = g_bar_epoch;
        if (atomicAdd(&g_bar_cnt, 1u) == NB - 1) {
            g_bar_cnt = 0;
            __threadfence();
            g_bar_epoch = e + 1;
        } else {
            while (g_bar_epoch == e) { }
            __threadfence();
        }
    }
    __syncthreads();
}

// =====================================================================
// K1: enc[b][e][n] = be[e] + sum_d te[b][n][d] * We[e][d]
// (unchanged — measured near FFMA2 roofline)
// =====================================================================
__global__ __launch_bounds__(256) void enc_kernel(
    const float* __restrict__ te, const float* __restrict__ We,
    const float* __restrict__ be)
{
    const int b  = blockIdx.z;
    const int n0 = blockIdx.x * 128;
    const int e0 = blockIdx.y * 128;

    __shared__ __align__(16) float As[16][132];
    __shared__ __align__(16) float Bs[16][132];

    const int tid = threadIdx.x;
    const int ty  = tid >> 4;
    const int tx  = tid & 15;

    unsigned long long acc[8][4];
#pragma unroll
    for (int i = 0; i < 8; i++)
#pragma unroll
        for (int j = 0; j < 4; j++) acc[i][j] = 0ULL;

    const int lrow = tid >> 2;
    const int lk4  = (tid & 3) * 4;
    const float* Aptr = We + (size_t)(e0 + lrow) * DD + lk4;
    const float* Bptr = te + ((size_t)b * NN + (n0 + lrow)) * DD + lk4;

    for (int k0 = 0; k0 < DD; k0 += 16) {
        float4 a0 = *(const float4*)(Aptr + k0);
        float4 a1 = *(const float4*)(Aptr + k0 + (size_t)64 * DD);
        float4 c0 = *(const float4*)(Bptr + k0);
        float4 c1 = *(const float4*)(Bptr + k0 + (size_t)64 * DD);
        As[lk4 + 0][lrow]      = a0.x; As[lk4 + 1][lrow]      = a0.y;
        As[lk4 + 2][lrow]      = a0.z; As[lk4 + 3][lrow]      = a0.w;
        As[lk4 + 0][lrow + 64] = a1.x; As[lk4 + 1][lrow + 64] = a1.y;
        As[lk4 + 2][lrow + 64] = a1.z; As[lk4 + 3][lrow + 64] = a1.w;
        Bs[lk4 + 0][lrow]      = c0.x; Bs[lk4 + 1][lrow]      = c0.y;
        Bs[lk4 + 2][lrow]      = c0.z; Bs[lk4 + 3][lrow]      = c0.w;
        Bs[lk4 + 0][lrow + 64] = c1.x; Bs[lk4 + 1][lrow + 64] = c1.y;
        Bs[lk4 + 2][lrow + 64] = c1.z; Bs[lk4 + 3][lrow + 64] = c1.w;
        __syncthreads();

#pragma unroll
        for (int kk = 0; kk < 16; kk++) {
            float4 av0 = *(const float4*)&As[kk][ty * 8];
            float4 av1 = *(const float4*)&As[kk][ty * 8 + 4];
            float4 bv0 = *(const float4*)&Bs[kk][tx * 8];
            float4 bv1 = *(const float4*)&Bs[kk][tx * 8 + 4];
            unsigned long long bp0 = pack2(bv0.x, bv0.y);
            unsigned long long bp1 = pack2(bv0.z, bv0.w);
            unsigned long long bp2 = pack2(bv1.x, bv1.y);
            unsigned long long bp3 = pack2(bv1.z, bv1.w);
            float av[8] = {av0.x, av0.y, av0.z, av0.w, av1.x, av1.y, av1.z, av1.w};
#pragma unroll
            for (int i = 0; i < 8; i++) {
                unsigned long long ad = pack2(av[i], av[i]);
                ffma2(acc[i][0], ad, bp0);
                ffma2(acc[i][1], ad, bp1);
                ffma2(acc[i][2], ad, bp2);
                ffma2(acc[i][3], ad, bp3);
            }
        }
        __syncthreads();
    }

#pragma unroll
    for (int i = 0; i < 8; i++) {
        const int e = e0 + ty * 8 + i;
        const float bias = __ldg(&be[e]);
        float* orow = g_enc + ((size_t)b * EE + e) * NN + n0 + tx * 8;
#pragma unroll
        for (int j = 0; j < 4; j++) {
            float x, y;
            unpack2(acc[i][j], x, y);
            float2 v = make_float2(x + bias, y + bias);
            *(float2*)(orow + 2 * j) = v;
        }
    }
}

// =====================================================================
// K0: g_dec_t[k][b] <- encoded_document[b][k]. grid 64, block 256
// =====================================================================
__global__ __launch_bounds__(256) void init_kernel(const float* __restrict__ encdoc)
{
    const int b = blockIdx.x, t = threadIdx.x;
#pragma unroll
    for (int i = 0; i < 4; i++) {
        const int k = i * 256 + t;
        g_dec_t[k * BB + b] = encdoc[(size_t)b * DD + k];
    }
}

// =====================================================================
// Persistent decode kernel: all TT steps, 5 phases/step, grid barriers.
// grid NB=128, block NT=256 (co-resident on <=148 SMs).
// =====================================================================
__global__ __launch_bounds__(NT, 1) void decode_kernel(
    const float* __restrict__ W_ih, const float* __restrict__ b_ih,
    const float* __restrict__ b_hh, const float* __restrict__ Wd,
    const float* __restrict__ bd,   const float* __restrict__ wr,
    const float* __restrict__ br,   const float* __restrict__ te,
    float* __restrict__ out, int write_idx)
{
    __shared__ __align__(16) float s_xs[2048];     // 8KB: x-stage / qc+wsm+part
    __shared__ __align__(16) float s_ws[2048];     // 8KB: weight stage
    __shared__ float s_wm[8]; __shared__ int s_wi[8];
    __shared__ float s_ss[8];
    __shared__ float s_m, s_lse; __shared__ int s_i;

    const int bid = blockIdx.x, t = threadIdx.x;
    const int ec = t >> 4, bq = t & 15;

    // Phase A constants (gates partials): 32 e-blocks x 4 k-quarters
    const int A_e0 = (bid & 31) * 16, A_kb = (bid >> 5) * 256;
    // Phase B constants: 1 output/thread
    const int B_idx = bid * NT + t;
    const int B_b = B_idx & 63, B_e = B_idx >> 6;
    const float B_gi0 = __ldg(&b_ih[B_e])          + __ldg(&b_hh[B_e]);
    const float B_gg0 = __ldg(&b_ih[2 * EE + B_e]) + __ldg(&b_hh[2 * EE + B_e]);
    const float B_go0 = __ldg(&b_ih[3 * EE + B_e]) + __ldg(&b_hh[3 * EE + B_e]);
    // Phase C constants: 32 e-blocks x 4 k-splits
    const int C_e0 = A_e0, C_ks = bid >> 5, C_kb = C_ks * 128;
    // Phase D constants: block owns one b, 4 n-chunks
    const int D_b = bid >> 1, D_half = bid & 1;
    const int nl = t & 63, qr = t >> 6;
    const float brv = __ldg(br);

    // wsum = sum(wr), once
    float wsum;
    {
        float v = __ldg(&wr[t]) + __ldg(&wr[t + 256]);
#pragma unroll
        for (int o = 16; o; o >>= 1) v += __shfl_xor_sync(0xffffffffu, v, o);
        if ((t & 31) == 0) s_ss[t >> 5] = v;
        __syncthreads();
        float v2 = 0.f;
#pragma unroll
        for (int w = 0; w < 8; w++) v2 += s_ss[w];
        wsum = v2;
        __syncthreads();
    }

    for (int step = 0; step < TT; step++) {
        // ================= Phase A: gate partials =================
        {
            unsigned long long acc[3][2];
#pragma unroll
            for (int g = 0; g < 3; g++) { acc[g][0] = 0ULL; acc[g][1] = 0ULL; }

            for (int c = 0; c < 8; c++) {
                const int kc = A_kb + c * 32;
#pragma unroll
                for (int i = 0; i < 2; i++) {
                    const int i4 = i * 256 + t;              // 512 float4s
                    const int kk = i4 >> 4, b4 = i4 & 15;
                    ((float4*)s_xs)[i4] = ldcg4(&g_dec_t[(kc + kk) * BB + b4 * 4]);
                }
#pragma unroll
                for (int gi = 0; gi < 3; gi++) {
                    const int row0 = (gi == 0 ? 0 : (gi == 1 ? 2 * EE : 3 * EE)) + A_e0;
#pragma unroll
                    for (int j = 0; j < 2; j++) {
                        const int idx = j * 256 + t;
                        const int kk = idx & 31, ee = idx >> 5;
                        s_ws[(ee * 32 + kk) * 4 + gi] =
                            __ldg(&W_ih[(size_t)(row0 + ee) * DD + kc + kk]);
                    }
                }
                __syncthreads();

#pragma unroll
                for (int kk = 0; kk < 32; kk++) {
                    float4 xv = *(const float4*)&s_xs[kk * 64 + bq * 4];
                    unsigned long long xp0 = pack2(xv.x, xv.y);
                    unsigned long long xp1 = pack2(xv.z, xv.w);
                    float4 wv = *(const float4*)&s_ws[(ec * 32 + kk) * 4];
                    unsigned long long w0 = pack2(wv.x, wv.x);
                    unsigned long long w1 = pack2(wv.y, wv.y);
                    unsigned long long w2 = pack2(wv.z, wv.z);
                    ffma2(acc[0][0], w0, xp0); ffma2(acc[0][1], w0, xp1);
                    ffma2(acc[1][0], w1, xp0); ffma2(acc[1][1], w1, xp1);
                    ffma2(acc[2][0], w2, xp0); ffma2(acc[2][1], w2, xp1);
                }
                __syncthreads();
            }
#pragma unroll
            for (int g = 0; g < 3; g++) {
                float a, b2, c2, d2;
                unpack2(acc[g][0], a, b2);
                unpack2(acc[g][1], c2, d2);
                *(float4*)&g_gpart[bid >> 5][g][A_e0 + ec][bq * 4] =
                    make_float4(a, b2, c2, d2);
            }
        }
        grid_barrier();

        // ================= Phase B: reduce + LSTM activation =================
        {
            float gi = B_gi0, gg = B_gg0, go = B_go0;
#pragma unroll
            for (int kq = 0; kq < 4; kq++) {
                gi += ldcg(&g_gpart[kq][0][B_e][B_b]);
                gg += ldcg(&g_gpart[kq][1][B_e][B_b]);
                go += ldcg(&g_gpart[kq][2][B_e][B_b]);
            }
            const float c = (1.f / (1.f + expf(-gi))) * tanhf(gg);
            g_hx_t[B_e * BB + B_b] = (1.f / (1.f + expf(-go))) * tanhf(c);
        }
        grid_barrier();

        // ================= Phase C: q partials =================
        {
            unsigned long long acc0 = 0ULL, acc1 = 0ULL;
            for (int c = 0; c < 4; c++) {
                const int kc = C_kb + c * 32;
#pragma unroll
                for (int i = 0; i < 2; i++) {
                    const int i4 = i * 256 + t;
                    const int kk = i4 >> 4, b4 = i4 & 15;
                    ((float4*)s_xs)[i4] = ldcg4(&g_hx_t[(kc + kk) * BB + b4 * 4]);
                }
#pragma unroll
                for (int j = 0; j < 2; j++) {
                    const int idx = j * 256 + t;
                    const int kk = idx & 31, ee = idx >> 5;
                    s_ws[ee * 32 + kk] = __ldg(&Wd[(size_t)(C_e0 + ee) * EE + kc + kk]);
                }
                __syncthreads();

#pragma unroll
                for (int kk = 0; kk < 32; kk++) {
                    float4 xv = *(const float4*)&s_xs[kk * 64 + bq * 4];
                    const float w = s_ws[ec * 32 + kk];
                    unsigned long long wp = pack2(w, w);
                    ffma2(acc0, wp, pack2(xv.x, xv.y));
                    ffma2(acc1, wp, pack2(xv.z, xv.w));
                }
                __syncthreads();
            }
            float a, b2, c2, d2;
            unpack2(acc0, a, b2);
            unpack2(acc1, c2, d2);
            const int b0 = bq * 4, e = C_e0 + ec;
            g_qpart[C_ks][b0 + 0][e] = a;
            g_qpart[C_ks][b0 + 1][e] = b2;
            g_qpart[C_ks][b0 + 2][e] = c2;
            g_qpart[C_ks][b0 + 3][e] = d2;
        }
        grid_barrier();

        // ================= Phase D: attention scores =================
        {
            // stage qc (pre-scaled) and wr for this block's b
#pragma unroll
            for (int j2 = 0; j2 < 2; j2++) {
                const int e = j2 * 256 + t;
                float q = __ldg(&bd[e]);
#pragma unroll
                for (int ks = 0; ks < 4; ks++) q += ldcg(&g_qpart[ks][D_b][e]);
                s_xs[e]       = C2L * q;
                s_xs[512 + e] = __ldg(&wr[e]);
            }
            __syncthreads();

            for (int j = 0; j < 4; j++) {
                const int nc = D_half * 4 + j;
                const int n  = nc * 64 + nl;
                const float* p = g_enc + ((size_t)D_b * EE + qr * 128) * NN + n;
                float acc = 0.f;
#pragma unroll 8
                for (int e = 0; e < 128; e++) {
                    const float v  = __ldg(p + (size_t)e * NN);
                    const int   eg = (qr << 7) + e;
                    const float a  = fmaf(C2L, v, s_xs[eg]);
                    acc = fmaf(s_xs[512 + eg], rcpa(ex2a(a) + 1.f), acc);
                }
                s_xs[1024 + qr * 64 + nl] = acc;
                __syncthreads();
                if (t < 64) {
                    const float s = wsum
                        - 2.f * (s_xs[1024 + t] + s_xs[1088 + t] +
                                 s_xs[1152 + t] + s_xs[1216 + t]) + brv;
                    g_scores[D_b * NN + nc * 64 + t] = s;
                }
                __syncthreads();
            }
        }
        grid_barrier();

        // ================= Phase E: log_softmax + argmax + gather =================
        if (bid < BB) {
            const int b = bid;
            const int lane = t & 31, w = t >> 5;
            const float s0 = ldcg(&g_scores[b * NN + t]);
            const float s1 = ldcg(&g_scores[b * NN + t + 256]);

            float m; int mi;
            if (s1 > s0) { m = s1; mi = t + 256; } else { m = s0; mi = t; }
#pragma unroll
            for (int o = 16; o; o >>= 1) {
                const float om = __shfl_xor_sync(0xffffffffu, m, o);
                const int   oi = __shfl_xor_sync(0xffffffffu, mi, o);
                if (om > m || (om == m && oi < mi)) { m = om; mi = oi; }
            }
            if (lane == 0) { s_wm[w] = m; s_wi[w] = mi; }
            __syncthreads();
            if (w == 0) {
                float m2 = (lane < 8) ? s_wm[lane] : -3.4e38f;
                int   i2 = (lane < 8) ? s_wi[lane] : 0;
#pragma unroll
                for (int o = 4; o; o >>= 1) {
                    const float om = __shfl_xor_sync(0xffffffffu, m2, o);
                    const int   oi = __shfl_xor_sync(0xffffffffu, i2, o);
                    if (om > m2 || (om == m2 && oi < i2)) { m2 = om; i2 = oi; }
                }
                if (lane == 0) { s_m = m2; s_i = i2; }
            }
            __syncthreads();
            const float mm  = s_m;
            const int   idx = s_i;

            float sum = expf(s0 - mm) + expf(s1 - mm);
#pragma unroll
            for (int o = 16; o; o >>= 1) sum += __shfl_xor_sync(0xffffffffu, sum, o);
            if (lane == 0) s_ss[w] = sum;
            __syncthreads();
            if (w == 0) {
                float s2 = (lane < 8) ? s_ss[lane] : 0.f;
#pragma unroll
                for (int o = 4; o; o >>= 1) s2 += __shfl_xor_sync(0xffffffffu, s2, o);
                if (lane == 0) s_lse = mm + logf(s2);
            }
            __syncthreads();
            const float lse = s_lse;

            float* orow = out + ((size_t)b * TT + step) * NN;
            orow[t]       = s0 - lse;
            orow[t + 256] = s1 - lse;

            // gather next decoder input -> transposed g_dec_t[k][b]
            const float* src = te + ((size_t)b * NN + idx) * DD;
#pragma unroll
            for (int i = 0; i < 4; i++) {
                const int k = i * 256 + t;
                g_dec_t[k * BB + b] = __ldg(&src[k]);
            }

            if (write_idx && t == 0)
                out[(size_t)BB * TT * NN + b * TT + step] = (float)idx;
        }
        grid_barrier();
    }
}

// =====================================================================
extern "C" void kernel_launch(void* const* d_in, const int* in_sizes, int n_in,
                              void* d_out, int out_size)
{
    const float* te     = (const float*)d_in[0];   // [64,512,1024]
    const float* encdoc = (const float*)d_in[1];   // [64,1024]
    const float* W_ih   = (const float*)d_in[2];   // [2048,1024]
    const float* b_ih   = (const float*)d_in[3];   // [2048]
    const float* b_hh   = (const float*)d_in[4];   // [2048]
    const float* Wd     = (const float*)d_in[5];   // [512,512]
    const float* bd     = (const float*)d_in[6];   // [512]
    const float* We     = (const float*)d_in[7];   // [512,1024]
    const float* be     = (const float*)d_in[8];   // [512]
    const float* wr     = (const float*)d_in[9];   // [1,512]
    const float* br     = (const float*)d_in[10];  // [1]

    float* out = (float*)d_out;
    const int write_idx = (out_size >= BB * TT * NN + BB * TT) ? 1 : 0;

    // Phase 1: loop-invariant encoder projection, stored [b][e][n]
    enc_kernel<<<dim3(NN / 128, EE / 128, BB), 256>>>(te, We, be);

    // Step-0 decoder input (transposed)
    init_kernel<<<BB, 256>>>(encdoc);

    // Entire 64-step decode in ONE persistent kernel
    decode_kernel<<<NB, NT>>>(W_ih, b_ih, b_hh, Wd, bd, wr, br, te, out, write_idx);
}

// round 7
// speedup vs baseline: 1.0679x; 1.0679x over previous
#include <cuda_runtime.h>
#include <cuda_bf16.h>

// Problem constants
#define BB 64      // batch
#define NN 512     // tokens
#define EE 512     // embed dim
#define DD 1024    // 2E
#define TT 64      // decode steps
#define NB 128     // persistent grid
#define NT 256     // persistent block

// ---------------- device scratch ----------------
__device__ float g_enc[(size_t)BB * EE * NN];   // [b][e][n]  64 MB, L2-resident
__device__ float g_dec_t[DD * BB];              // decoder input, TRANSPOSED [k][b]
__device__ float g_gpart[4][3][EE][BB];         // gate partials [kq][gate][e][b]
__device__ float g_hx_t[EE * BB];               // hx transposed [e(=k')][b]
__device__ float g_qpart[4][BB][EE];            // q partials [ks][b][e]
__device__ float g_scores[BB * NN];
__device__ unsigned g_pcnt[TT * 5];             // one-shot barrier counters

// ---------------- packed fp32x2 helpers (sm_103a FFMA2) ----------------
__device__ __forceinline__ unsigned long long pack2(float x, float y) {
    unsigned long long r;
    asm("mov.b64 %0, {%1,%2};" : "=l"(r) : "f"(x), "f"(y));
    return r;
}
__device__ __forceinline__ void unpack2(unsigned long long v, float& x, float& y) {
    asm("mov.b64 {%0,%1}, %2;" : "=f"(x), "=f"(y) : "l"(v));
}
__device__ __forceinline__ void ffma2(unsigned long long& d, unsigned long long a, unsigned long long b) {
    asm("fma.rn.f32x2 %0, %1, %2, %0;" : "+l"(d) : "l"(a), "l"(b));
}
__device__ __forceinline__ float ex2a(float x) {
    float r; asm("ex2.approx.f32 %0, %1;" : "=f"(r) : "f"(x)); return r;
}
__device__ __forceinline__ float rcpa(float x) {
    float r; asm("rcp.approx.f32 %0, %1;" : "=f"(r) : "f"(x)); return r;
}
__device__ __forceinline__ float ldcg(const float* p) {
    float r; asm volatile("ld.global.cg.f32 %0, [%1];" : "=f"(r) : "l"(p)); return r;
}
__device__ __forceinline__ float4 ldcg4(const float* p) {
    float4 v;
    asm volatile("ld.global.cg.v4.f32 {%0,%1,%2,%3}, [%4];"
                 : "=f"(v.x), "=f"(v.y), "=f"(v.z), "=f"(v.w) : "l"(p));
    return v;
}

#define C2L 2.885390081777926f   // 2*log2(e)

// ---------------- grid barrier: one-shot counter + nanosleep spin ----------------
__device__ __forceinline__ void grid_bar(int slot) {
    __syncthreads();
    if (threadIdx.x == 0) {
        __threadfence();
        const unsigned arrived = atomicAdd(&g_pcnt[slot], 1u) + 1u;
        if (arrived != NB) {
            volatile unsigned* p = &g_pcnt[slot];
            while (*p != NB) __nanosleep(32);
        }
    }
    __syncthreads();
}

// =====================================================================
// K1: enc[b][e][n] = be[e] + sum_d te[b][n][d] * We[e][d]
// (unchanged — near FFMA2 roofline)
// =====================================================================
__global__ __launch_bounds__(256) void enc_kernel(
    const float* __restrict__ te, const float* __restrict__ We,
    const float* __restrict__ be)
{
    const int b  = blockIdx.z;
    const int n0 = blockIdx.x * 128;
    const int e0 = blockIdx.y * 128;

    __shared__ __align__(16) float As[16][132];
    __shared__ __align__(16) float Bs[16][132];

    const int tid = threadIdx.x;
    const int ty  = tid >> 4;
    const int tx  = tid & 15;

    unsigned long long acc[8][4];
#pragma unroll
    for (int i = 0; i < 8; i++)
#pragma unroll
        for (int j = 0; j < 4; j++) acc[i][j] = 0ULL;

    const int lrow = tid >> 2;
    const int lk4  = (tid & 3) * 4;
    const float* Aptr = We + (size_t)(e0 + lrow) * DD + lk4;
    const float* Bptr = te + ((size_t)b * NN + (n0 + lrow)) * DD + lk4;

    for (int k0 = 0; k0 < DD; k0 += 16) {
        float4 a0 = *(const float4*)(Aptr + k0);
        float4 a1 = *(const float4*)(Aptr + k0 + (size_t)64 * DD);
        float4 c0 = *(const float4*)(Bptr + k0);
        float4 c1 = *(const float4*)(Bptr + k0 + (size_t)64 * DD);
        As[lk4 + 0][lrow]      = a0.x; As[lk4 + 1][lrow]      = a0.y;
        As[lk4 + 2][lrow]      = a0.z; As[lk4 + 3][lrow]      = a0.w;
        As[lk4 + 0][lrow + 64] = a1.x; As[lk4 + 1][lrow + 64] = a1.y;
        As[lk4 + 2][lrow + 64] = a1.z; As[lk4 + 3][lrow + 64] = a1.w;
        Bs[lk4 + 0][lrow]      = c0.x; Bs[lk4 + 1][lrow]      = c0.y;
        Bs[lk4 + 2][lrow]      = c0.z; Bs[lk4 + 3][lrow]      = c0.w;
        Bs[lk4 + 0][lrow + 64] = c1.x; Bs[lk4 + 1][lrow + 64] = c1.y;
        Bs[lk4 + 2][lrow + 64] = c1.z; Bs[lk4 + 3][lrow + 64] = c1.w;
        __syncthreads();

#pragma unroll
        for (int kk = 0; kk < 16; kk++) {
            float4 av0 = *(const float4*)&As[kk][ty * 8];
            float4 av1 = *(const float4*)&As[kk][ty * 8 + 4];
            float4 bv0 = *(const float4*)&Bs[kk][tx * 8];
            float4 bv1 = *(const float4*)&Bs[kk][tx * 8 + 4];
            unsigned long long bp0 = pack2(bv0.x, bv0.y);
            unsigned long long bp1 = pack2(bv0.z, bv0.w);
            unsigned long long bp2 = pack2(bv1.x, bv1.y);
            unsigned long long bp3 = pack2(bv1.z, bv1.w);
            float av[8] = {av0.x, av0.y, av0.z, av0.w, av1.x, av1.y, av1.z, av1.w};
#pragma unroll
            for (int i = 0; i < 8; i++) {
                unsigned long long ad = pack2(av[i], av[i]);
                ffma2(acc[i][0], ad, bp0);
                ffma2(acc[i][1], ad, bp1);
                ffma2(acc[i][2], ad, bp2);
                ffma2(acc[i][3], ad, bp3);
            }
        }
        __syncthreads();
    }

#pragma unroll
    for (int i = 0; i < 8; i++) {
        const int e = e0 + ty * 8 + i;
        const float bias = __ldg(&be[e]);
        float* orow = g_enc + ((size_t)b * EE + e) * NN + n0 + tx * 8;
#pragma unroll
        for (int j = 0; j < 4; j++) {
            float x, y;
            unpack2(acc[i][j], x, y);
            float2 v = make_float2(x + bias, y + bias);
            *(float2*)(orow + 2 * j) = v;
        }
    }
}

// =====================================================================
// K0: g_dec_t[k][b] <- encoded_document[b][k]; zero barrier counters.
// grid 64, block 256
// =====================================================================
__global__ __launch_bounds__(256) void init_kernel(const float* __restrict__ encdoc)
{
    const int b = blockIdx.x, t = threadIdx.x;
#pragma unroll
    for (int i = 0; i < 4; i++) {
        const int k = i * 256 + t;
        g_dec_t[k * BB + b] = encdoc[(size_t)b * DD + k];
    }
    const int gid = b * 256 + t;
    if (gid < TT * 5) g_pcnt[gid] = 0u;
}

// =====================================================================
// Persistent decode kernel: all TT steps, 5 phases/step, fast barriers.
// grid NB=128, block NT=256 (co-resident on <=148 SMs).
// =====================================================================
__global__ __launch_bounds__(NT, 1) void decode_kernel(
    const float* __restrict__ W_ih, const float* __restrict__ b_ih,
    const float* __restrict__ b_hh, const float* __restrict__ Wd,
    const float* __restrict__ bd,   const float* __restrict__ wr,
    const float* __restrict__ br,   const float* __restrict__ te,
    float* __restrict__ out, int write_idx)
{
    __shared__ __align__(16) float s_xs[2048];     // 8KB: x-stage / qc+part
    __shared__ __align__(16) float s_ws[2048];     // 8KB: weight stage
    __shared__ float s_wr[EE];                     // wr staged once
    __shared__ float s_wm[8]; __shared__ int s_wi[8];
    __shared__ float s_ss[8];
    __shared__ float s_m, s_lse; __shared__ int s_i;

    const int bid = blockIdx.x, t = threadIdx.x;
    const int ec = t >> 4, bq = t & 15;

    // Phase A constants (gates partials): 32 e-blocks x 4 k-quarters
    const int A_e0 = (bid & 31) * 16, A_kb = (bid >> 5) * 256;
    // Phase B constants: 1 output/thread
    const int B_idx = bid * NT + t;
    const int B_b = B_idx & 63, B_e = B_idx >> 6;
    const float B_gi0 = __ldg(&b_ih[B_e])          + __ldg(&b_hh[B_e]);
    const float B_gg0 = __ldg(&b_ih[2 * EE + B_e]) + __ldg(&b_hh[2 * EE + B_e]);
    const float B_go0 = __ldg(&b_ih[3 * EE + B_e]) + __ldg(&b_hh[3 * EE + B_e]);
    // Phase C constants: 32 e-blocks x 4 k-splits
    const int C_e0 = A_e0, C_ks = bid >> 5, C_kb = C_ks * 128;
    // Phase D constants: block owns one b, 4 n-chunks
    const int D_b = bid >> 1, D_half = bid & 1;
    const int nl = t & 63, qr = t >> 6;
    const float brv = __ldg(br);

    // stage wr once + wsum
    float wsum;
    {
        const float w0 = __ldg(&wr[t]), w1 = __ldg(&wr[t + 256]);
        s_wr[t] = w0; s_wr[t + 256] = w1;
        float v = w0 + w1;
#pragma unroll
        for (int o = 16; o; o >>= 1) v += __shfl_xor_sync(0xffffffffu, v, o);
        if ((t & 31) == 0) s_ss[t >> 5] = v;
        __syncthreads();
        float v2 = 0.f;
#pragma unroll
        for (int w = 0; w < 8; w++) v2 += s_ss[w];
        wsum = v2;
        __syncthreads();
    }

    for (int step = 0; step < TT; step++) {
        // ================= Phase A: gate partials =================
        {
            unsigned long long acc[3][2];
#pragma unroll
            for (int g = 0; g < 3; g++) { acc[g][0] = 0ULL; acc[g][1] = 0ULL; }

            for (int c = 0; c < 8; c++) {
                const int kc = A_kb + c * 32;
#pragma unroll
                for (int i = 0; i < 2; i++) {
                    const int i4 = i * 256 + t;              // 512 float4s
                    const int kk = i4 >> 4, b4 = i4 & 15;
                    ((float4*)s_xs)[i4] = ldcg4(&g_dec_t[(kc + kk) * BB + b4 * 4]);
                }
#pragma unroll
                for (int gi = 0; gi < 3; gi++) {
                    const int row0 = (gi == 0 ? 0 : (gi == 1 ? 2 * EE : 3 * EE)) + A_e0;
#pragma unroll
                    for (int j = 0; j < 2; j++) {
                        const int idx = j * 256 + t;
                        const int kk = idx & 31, ee = idx >> 5;
                        s_ws[(ee * 32 + kk) * 4 + gi] =
                            __ldg(&W_ih[(size_t)(row0 + ee) * DD + kc + kk]);
                    }
                }
                __syncthreads();

#pragma unroll
                for (int kk = 0; kk < 32; kk++) {
                    float4 xv = *(const float4*)&s_xs[kk * 64 + bq * 4];
                    unsigned long long xp0 = pack2(xv.x, xv.y);
                    unsigned long long xp1 = pack2(xv.z, xv.w);
                    float4 wv = *(const float4*)&s_ws[(ec * 32 + kk) * 4];
                    unsigned long long w0 = pack2(wv.x, wv.x);
                    unsigned long long w1 = pack2(wv.y, wv.y);
                    unsigned long long w2 = pack2(wv.z, wv.z);
                    ffma2(acc[0][0], w0, xp0); ffma2(acc[0][1], w0, xp1);
                    ffma2(acc[1][0], w1, xp0); ffma2(acc[1][1], w1, xp1);
                    ffma2(acc[2][0], w2, xp0); ffma2(acc[2][1], w2, xp1);
                }
                __syncthreads();
            }
#pragma unroll
            for (int g = 0; g < 3; g++) {
                float a, b2, c2, d2;
                unpack2(acc[g][0], a, b2);
                unpack2(acc[g][1], c2, d2);
                *(float4*)&g_gpart[bid >> 5][g][A_e0 + ec][bq * 4] =
                    make_float4(a, b2, c2, d2);
            }
        }
        grid_bar(step * 5 + 0);

        // ================= Phase B: reduce + LSTM activation =================
        {
            float gi = B_gi0, gg = B_gg0, go = B_go0;
#pragma unroll
            for (int kq = 0; kq < 4; kq++) {
                gi += ldcg(&g_gpart[kq][0][B_e][B_b]);
                gg += ldcg(&g_gpart[kq][1][B_e][B_b]);
                go += ldcg(&g_gpart[kq][2][B_e][B_b]);
            }
            const float c = (1.f / (1.f + expf(-gi))) * tanhf(gg);
            g_hx_t[B_e * BB + B_b] = (1.f / (1.f + expf(-go))) * tanhf(c);
        }
        grid_bar(step * 5 + 1);

        // ================= Phase C: q partials =================
        {
            unsigned long long acc0 = 0ULL, acc1 = 0ULL;
            for (int c = 0; c < 4; c++) {
                const int kc = C_kb + c * 32;
#pragma unroll
                for (int i = 0; i < 2; i++) {
                    const int i4 = i * 256 + t;
                    const int kk = i4 >> 4, b4 = i4 & 15;
                    ((float4*)s_xs)[i4] = ldcg4(&g_hx_t[(kc + kk) * BB + b4 * 4]);
                }
#pragma unroll
                for (int j = 0; j < 2; j++) {
                    const int idx = j * 256 + t;
                    const int kk = idx & 31, ee = idx >> 5;
                    s_ws[ee * 32 + kk] = __ldg(&Wd[(size_t)(C_e0 + ee) * EE + kc + kk]);
                }
                __syncthreads();

#pragma unroll
                for (int kk = 0; kk < 32; kk++) {
                    float4 xv = *(const float4*)&s_xs[kk * 64 + bq * 4];
                    const float w = s_ws[ec * 32 + kk];
                    unsigned long long wp = pack2(w, w);
                    ffma2(acc0, wp, pack2(xv.x, xv.y));
                    ffma2(acc1, wp, pack2(xv.z, xv.w));
                }
                __syncthreads();
            }
            float a, b2, c2, d2;
            unpack2(acc0, a, b2);
            unpack2(acc1, c2, d2);
            const int b0 = bq * 4, e = C_e0 + ec;
            g_qpart[C_ks][b0 + 0][e] = a;
            g_qpart[C_ks][b0 + 1][e] = b2;
            g_qpart[C_ks][b0 + 2][e] = c2;
            g_qpart[C_ks][b0 + 3][e] = d2;
        }
        grid_bar(step * 5 + 2);

        // ================= Phase D: attention scores =================
        {
            // stage qc (pre-scaled) for this block's b
#pragma unroll
            for (int j2 = 0; j2 < 2; j2++) {
                const int e = j2 * 256 + t;
                float q = __ldg(&bd[e]);
#pragma unroll
                for (int ks = 0; ks < 4; ks++) q += ldcg(&g_qpart[ks][D_b][e]);
                s_xs[e] = C2L * q;
            }
            __syncthreads();

            for (int j = 0; j < 4; j++) {
                const int nc = D_half * 4 + j;
                const int n  = nc * 64 + nl;
                const float* p = g_enc + ((size_t)D_b * EE + qr * 128) * NN + n;
                float acc = 0.f;
#pragma unroll 8
                for (int e = 0; e < 128; e++) {
                    const float v  = __ldg(p + (size_t)e * NN);
                    const int   eg = (qr << 7) + e;
                    const float a  = fmaf(C2L, v, s_xs[eg]);
                    acc = fmaf(s_wr[eg], rcpa(ex2a(a) + 1.f), acc);
                }
                s_xs[1024 + qr * 64 + nl] = acc;
                __syncthreads();
                if (t < 64) {
                    const float s = wsum
                        - 2.f * (s_xs[1024 + t] + s_xs[1088 + t] +
                                 s_xs[1152 + t] + s_xs[1216 + t]) + brv;
                    g_scores[D_b * NN + nc * 64 + t] = s;
                }
                __syncthreads();
            }
        }
        grid_bar(step * 5 + 3);

        // ================= Phase E: log_softmax + argmax + gather =================
        if (bid < BB) {
            const int b = bid;
            const int lane = t & 31, w = t >> 5;
            const float s0 = ldcg(&g_scores[b * NN + t]);
            const float s1 = ldcg(&g_scores[b * NN + t + 256]);

            float m; int mi;
            if (s1 > s0) { m = s1; mi = t + 256; } else { m = s0; mi = t; }
#pragma unroll
            for (int o = 16; o; o >>= 1) {
                const float om = __shfl_xor_sync(0xffffffffu, m, o);
                const int   oi = __shfl_xor_sync(0xffffffffu, mi, o);
                if (om > m || (om == m && oi < mi)) { m = om; mi = oi; }
            }
            if (lane == 0) { s_wm[w] = m; s_wi[w] = mi; }
            __syncthreads();
            if (w == 0) {
                float m2 = (lane < 8) ? s_wm[lane] : -3.4e38f;
                int   i2 = (lane < 8) ? s_wi[lane] : 0;
#pragma unroll
                for (int o = 4; o; o >>= 1) {
                    const float om = __shfl_xor_sync(0xffffffffu, m2, o);
                    const int   oi = __shfl_xor_sync(0xffffffffu, i2, o);
                    if (om > m2 || (om == m2 && oi < i2)) { m2 = om; i2 = oi; }
                }
                if (lane == 0) { s_m = m2; s_i = i2; }
            }
            __syncthreads();
            const float mm  = s_m;
            const int   idx = s_i;

            float sum = expf(s0 - mm) + expf(s1 - mm);
#pragma unroll
            for (int o = 16; o; o >>= 1) sum += __shfl_xor_sync(0xffffffffu, sum, o);
            if (lane == 0) s_ss[w] = sum;
            __syncthreads();
            if (w == 0) {
                float s2 = (lane < 8) ? s_ss[lane] : 0.f;
#pragma unroll
                for (int o = 4; o; o >>= 1) s2 += __shfl_xor_sync(0xffffffffu, s2, o);
                if (lane == 0) s_lse = mm + logf(s2);
            }
            __syncthreads();
            const float lse = s_lse;

            float* orow = out + ((size_t)b * TT + step) * NN;
            orow[t]       = s0 - lse;
            orow[t + 256] = s1 - lse;

            // gather next decoder input -> transposed g_dec_t[k][b]
            const float* src = te + ((size_t)b * NN + idx) * DD;
#pragma unroll
            for (int i = 0; i < 4; i++) {
                const int k = i * 256 + t;
                g_dec_t[k * BB + b] = __ldg(&src[k]);
            }

            if (write_idx && t == 0)
                out[(size_t)BB * TT * NN + b * TT + step] = (float)idx;
        }
        grid_bar(step * 5 + 4);
    }
}

// =====================================================================
extern "C" void kernel_launch(void* const* d_in, const int* in_sizes, int n_in,
                              void* d_out, int out_size)
{
    const float* te     = (const float*)d_in[0];   // [64,512,1024]
    const float* encdoc = (const float*)d_in[1];   // [64,1024]
    const float* W_ih   = (const float*)d_in[2];   // [2048,1024]
    const float* b_ih   = (const float*)d_in[3];   // [2048]
    const float* b_hh   = (const float*)d_in[4];   // [2048]
    const float* Wd     = (const float*)d_in[5];   // [512,512]
    const float* bd     = (const float*)d_in[6];   // [512]
    const float* We     = (const float*)d_in[7];   // [512,1024]
    const float* be     = (const float*)d_in[8];   // [512]
    const float* wr     = (const float*)d_in[9];   // [1,512]
    const float* br     = (const float*)d_in[10];  // [1]

    float* out = (float*)d_out;
    const int write_idx = (out_size >= BB * TT * NN + BB * TT) ? 1 : 0;

    // Phase 1: loop-invariant encoder projection, stored [b][e][n]
    enc_kernel<<<dim3(NN / 128, EE / 128, BB), 256>>>(te, We, be);

    // Step-0 decoder input (transposed) + barrier counter reset
    init_kernel<<<BB, 256>>>(encdoc);

    // Entire 64-step decode in ONE persistent kernel
    decode_kernel<<<NB, NT>>>(W_ih, b_ih, b_hh, Wd, bd, wr, br, te, out, write_idx);
}